// round 2
// baseline (speedup 1.0000x reference)
#include <cuda_runtime.h>
#include <cstdint>

#define NN 110592
#define CC 128
#define C3 384
#define BB 2
#define GR_BLOCKS 160
#define GEMM_SMEM (2 * 128 * 136 * 4)
#define GRAM_SMEM (512 * 33 * 4)

__device__ float g_qkv[(size_t)BB * C3 * NN];
__device__ float g_dw [(size_t)BB * C3 * NN];
__device__ float g_gram[BB * 8 * 16 * 16];
__device__ float g_ssq [BB * 2 * CC];
__device__ float g_W   [BB * CC * CC];

__device__ __forceinline__ void cp16(void* s, const void* g) {
    unsigned sa = (unsigned)__cvta_generic_to_shared(s);
    asm volatile("cp.async.cg.shared.global [%0], [%1], 16;" :: "r"(sa), "l"(g) : "memory");
}
__device__ __forceinline__ unsigned f2tf(float f) {
    unsigned u; asm("cvt.rna.tf32.f32 %0, %1;" : "=r"(u) : "f"(f)); return u;
}
__device__ __forceinline__ void mma8(float* d, const unsigned* a, const unsigned* b) {
    asm volatile("mma.sync.aligned.m16n8k8.row.col.f32.tf32.tf32.f32 "
                 "{%0,%1,%2,%3}, {%4,%5,%6,%7}, {%8,%9}, {%0,%1,%2,%3};"
                 : "+f"(d[0]), "+f"(d[1]), "+f"(d[2]), "+f"(d[3])
                 : "r"(a[0]), "r"(a[1]), "r"(a[2]), "r"(a[3]), "r"(b[0]), "r"(b[1]));
}

__global__ void zero_k() {
    int t = blockIdx.x * 256 + threadIdx.x;
    if (t < BB * 8 * 16 * 16) g_gram[t] = 0.f;
    if (t < BB * 2 * CC)      g_ssq[t]  = 0.f;
}

// C[mt*128+.., bn*128+..] = A[mt] (128x128) @ B (128 x NN tile), TF32 MMA.
__global__ __launch_bounds__(256) void gemm_k(
    const float* __restrict__ A, long long aBatch, long long aTile, int MT,
    const float* __restrict__ B, long long bBatch,
    float* __restrict__ C, long long cBatch)
{
    extern __shared__ float sm[];
    float* sA = sm;              // [128][136]
    float* sB = sm + 128 * 136;  // [128][136]
    const int tid = threadIdx.x;
    const int bn = blockIdx.x, bb = blockIdx.y;
    const float* Ab = A + (long long)bb * aBatch;
    const float* Bb = B + (long long)bb * bBatch + (long long)bn * 128;
    float* Cb = C + (long long)bb * cBatch + (long long)bn * 128;

    #pragma unroll
    for (int i = 0; i < 16; i++) {
        int l = i * 256 + tid;
        int r = l >> 5, c4 = l & 31;
        cp16(&sB[r * 136 + c4 * 4], Bb + (long long)r * NN + c4 * 4);
    }
    asm volatile("cp.async.commit_group;" ::: "memory");

    const int warp = tid >> 5, lane = tid & 31;
    const int wm = warp >> 2, wn = warp & 3;
    const int lr = lane >> 2, lc = lane & 3;

    for (int mt = 0; mt < MT; mt++) {
        const float* At = Ab + mt * aTile;
        #pragma unroll
        for (int i = 0; i < 16; i++) {
            int l = i * 256 + tid;
            int r = l >> 5, c4 = l & 31;
            cp16(&sA[r * 136 + c4 * 4], At + r * 128 + c4 * 4);
        }
        asm volatile("cp.async.commit_group;" ::: "memory");
        asm volatile("cp.async.wait_group 0;" ::: "memory");
        __syncthreads();

        float acc[4][4][4];
        #pragma unroll
        for (int a = 0; a < 4; a++)
            #pragma unroll
            for (int b = 0; b < 4; b++)
                #pragma unroll
                for (int r = 0; r < 4; r++) acc[a][b][r] = 0.f;

        #pragma unroll
        for (int ks = 0; ks < 16; ks++) {
            const int k = ks * 8;
            unsigned af[4][4], bf[4][2];
            #pragma unroll
            for (int mi = 0; mi < 4; mi++) {
                int m0 = wm * 64 + mi * 16;
                af[mi][0] = f2tf(sA[(m0 + lr) * 136 + k + lc]);
                af[mi][1] = f2tf(sA[(m0 + 8 + lr) * 136 + k + lc]);
                af[mi][2] = f2tf(sA[(m0 + lr) * 136 + k + 4 + lc]);
                af[mi][3] = f2tf(sA[(m0 + 8 + lr) * 136 + k + 4 + lc]);
            }
            #pragma unroll
            for (int ni = 0; ni < 4; ni++) {
                int n0 = wn * 32 + ni * 8;
                bf[ni][0] = f2tf(sB[(k + lc) * 136 + n0 + lr]);
                bf[ni][1] = f2tf(sB[(k + 4 + lc) * 136 + n0 + lr]);
            }
            #pragma unroll
            for (int mi = 0; mi < 4; mi++)
                #pragma unroll
                for (int ni = 0; ni < 4; ni++)
                    mma8(acc[mi][ni], af[mi], bf[ni]);
        }
        __syncthreads();

        #pragma unroll
        for (int mi = 0; mi < 4; mi++) {
            int m0 = mt * 128 + wm * 64 + mi * 16;
            #pragma unroll
            for (int ni = 0; ni < 4; ni++) {
                int n0 = wn * 32 + ni * 8;
                float2 v0 = make_float2(acc[mi][ni][0], acc[mi][ni][1]);
                float2 v1 = make_float2(acc[mi][ni][2], acc[mi][ni][3]);
                *(float2*)(Cb + (long long)(m0 + lr) * NN + n0 + lc * 2) = v0;
                *(float2*)(Cb + (long long)(m0 + 8 + lr) * NN + n0 + lc * 2) = v1;
            }
        }
    }
}

// depthwise 3x3x3, pad 1. block = (h, ch, b), threads (48 d, 2 w-halves).
__global__ __launch_bounds__(96) void dwconv_k(
    const float* __restrict__ in, const float* __restrict__ wg,
    float* __restrict__ out)
{
    __shared__ float sP[3][50][56];
    __shared__ float sred[96];
    const int h = blockIdx.x, ch = blockIdx.y, b = blockIdx.z;
    const int tx = threadIdx.x, ty = threadIdx.y;
    const int tid = ty * 48 + tx;

    float* sf = &sP[0][0][0];
    for (int i = tid; i < 3 * 50 * 56; i += 96) sf[i] = 0.f;
    __syncthreads();

    const float* base = in + ((long long)(b * C3 + ch) * 48) * 2304;
    #pragma unroll
    for (int hp = 0; hp < 3; hp++) {
        int hh = h - 1 + hp;
        if (hh < 0 || hh >= 48) continue;
        const float* pl = base + (long long)hh * 2304;
        for (int l = tid; l < 576; l += 96) {
            int wr = l / 12, q = l % 12;
            float4 v = *(const float4*)(pl + wr * 48 + q * 4);
            *(float4*)(&sP[hp][wr + 1][4 + q * 4]) = v;
        }
    }
    __syncthreads();

    float wv[27];
    const float* wp = wg + ch * 27;
    #pragma unroll
    for (int i = 0; i < 27; i++) wv[i] = wp[i];

    const int d = tx;
    const int w0 = ty * 24;
    float r[3][3][3];  // [slot][hp][dp]
    #pragma unroll
    for (int hp = 0; hp < 3; hp++)
        #pragma unroll
        for (int dp = 0; dp < 3; dp++) {
            r[0][hp][dp] = sP[hp][w0][d + 3 + dp];
            r[1][hp][dp] = sP[hp][w0 + 1][d + 3 + dp];
        }

    float lssq = 0.f;
    float* ob = out + ((long long)(b * C3 + ch) * 48 + h) * 2304;
    #pragma unroll
    for (int k = 0; k < 24; k++) {
        const int ns = (k + 2) % 3;
        #pragma unroll
        for (int hp = 0; hp < 3; hp++)
            #pragma unroll
            for (int dp = 0; dp < 3; dp++)
                r[ns][hp][dp] = sP[hp][w0 + k + 2][d + 3 + dp];
        float o = 0.f;
        #pragma unroll
        for (int hp = 0; hp < 3; hp++)
            #pragma unroll
            for (int q = 0; q < 3; q++) {
                const int sl = (k + q) % 3;
                #pragma unroll
                for (int dp = 0; dp < 3; dp++)
                    o += wv[hp * 9 + q * 3 + dp] * r[sl][hp][dp];
            }
        ob[(w0 + k) * 48 + d] = o;
        lssq += o * o;
    }

    if (ch < 256) {
        sred[tid] = lssq;
        __syncthreads();
        if (tid < 32) {
            float v = sred[tid] + sred[tid + 32] + sred[tid + 64];
            #pragma unroll
            for (int off = 16; off > 0; off >>= 1)
                v += __shfl_down_sync(0xffffffffu, v, off);
            if (tid == 0) atomicAdd(&g_ssq[b * 256 + ch], v);
        }
    }
}

// G[b,h,i,j] = sum_n q[i,n]*k[j,n]. 256 thr: bh = tid>>4, it=(tid>>2)&3, jt=tid&3.
__global__ __launch_bounds__(256) void gram_k(const float* __restrict__ dw) {
    extern __shared__ float sq[];  // [512][33]
    const int tid = threadIdx.x;
    const int bh = tid >> 4;
    const int b = bh >> 3, h = bh & 7;
    const int it = (tid >> 2) & 3, jt = tid & 3;

    float acc[4][4];
    #pragma unroll
    for (int a = 0; a < 4; a++)
        #pragma unroll
        for (int c = 0; c < 4; c++) acc[a][c] = 0.f;

    const int qbase = (b * 256 + h * 16 + it * 4) * 33;
    const int kbase = (b * 256 + 128 + h * 16 + jt * 4) * 33;

    for (int c = blockIdx.x; c < NN / 32; c += GR_BLOCKS) {
        const long long n0 = (long long)c * 32;
        #pragma unroll
        for (int i = 0; i < 16; i++) {
            int l = i * 256 + tid;
            int rr = l >> 3, q = l & 7;
            float4 v = *(const float4*)(dw + ((long long)((rr >> 8) * C3 + (rr & 255))) * NN + n0 + q * 4);
            sq[rr * 33 + q * 4 + 0] = v.x;
            sq[rr * 33 + q * 4 + 1] = v.y;
            sq[rr * 33 + q * 4 + 2] = v.z;
            sq[rr * 33 + q * 4 + 3] = v.w;
        }
        __syncthreads();
        #pragma unroll 4
        for (int n = 0; n < 32; n++) {
            float qv[4], kv[4];
            #pragma unroll
            for (int ii = 0; ii < 4; ii++) qv[ii] = sq[qbase + ii * 33 + n];
            #pragma unroll
            for (int jj = 0; jj < 4; jj++) kv[jj] = sq[kbase + jj * 33 + n];
            #pragma unroll
            for (int ii = 0; ii < 4; ii++)
                #pragma unroll
                for (int jj = 0; jj < 4; jj++)
                    acc[ii][jj] += qv[ii] * kv[jj];
        }
        __syncthreads();
    }
    #pragma unroll
    for (int ii = 0; ii < 4; ii++)
        #pragma unroll
        for (int jj = 0; jj < 4; jj++) {
            int i = it * 4 + ii, j = jt * 4 + jj;
            atomicAdd(&g_gram[((b * 8 + h) * 16 + i) * 16 + j], acc[ii][jj]);
        }
}

// softmax + W_b = proj_w @ blockdiag(attn_b). one block per batch.
__global__ __launch_bounds__(256) void fold_k(
    const float* __restrict__ proj_w, const float* __restrict__ temp)
{
    __shared__ float sat[8][16][17];
    const int b = blockIdx.x, tid = threadIdx.x;
    if (tid < 128) {
        const int h = tid >> 4, i = tid & 15;
        float nq = fmaxf(sqrtf(g_ssq[b * 256 + h * 16 + i]), 1e-12f);
        float tv = temp[h];
        float row[16];
        float mx = -1e30f;
        #pragma unroll
        for (int j = 0; j < 16; j++) {
            float nk = fmaxf(sqrtf(g_ssq[b * 256 + 128 + h * 16 + j]), 1e-12f);
            float v = g_gram[((b * 8 + h) * 16 + i) * 16 + j] / (nq * nk) * tv;
            row[j] = v;
            mx = fmaxf(mx, v);
        }
        float s = 0.f;
        #pragma unroll
        for (int j = 0; j < 16; j++) { row[j] = expf(row[j] - mx); s += row[j]; }
        const float inv = 1.f / s;
        #pragma unroll
        for (int j = 0; j < 16; j++) sat[h][i][j] = row[j] * inv;
    }
    __syncthreads();
    for (int idx = tid; idx < 16384; idx += 256) {
        const int o = idx >> 7, col = idx & 127;
        const int h = col >> 4, j = col & 15;
        float s = 0.f;
        #pragma unroll
        for (int i = 0; i < 16; i++)
            s += proj_w[o * 128 + h * 16 + i] * sat[h][i][j];
        g_W[b * 16384 + idx] = s;
    }
}

extern "C" void kernel_launch(void* const* d_in, const int* in_sizes, int n_in,
                              void* d_out, int out_size) {
    const float* x      = (const float*)d_in[0];
    const float* qkv_w  = (const float*)d_in[1];
    const float* dw_w   = (const float*)d_in[2];
    const float* proj_w = (const float*)d_in[3];
    const float* temp   = (const float*)d_in[4];
    float* out = (float*)d_out;

    void *p_qkv = nullptr, *p_dw = nullptr, *p_W = nullptr;
    cudaGetSymbolAddress(&p_qkv, g_qkv);
    cudaGetSymbolAddress(&p_dw,  g_dw);
    cudaGetSymbolAddress(&p_W,   g_W);

    cudaFuncSetAttribute(gemm_k, cudaFuncAttributeMaxDynamicSharedMemorySize, GEMM_SMEM);
    cudaFuncSetAttribute(gram_k, cudaFuncAttributeMaxDynamicSharedMemorySize, GRAM_SMEM);

    zero_k<<<16, 256>>>();

    // qkv = qkv_w @ x   (per batch, M=384 via 3 m-tiles)
    gemm_k<<<dim3(NN / 128, BB), 256, GEMM_SMEM>>>(
        qkv_w, 0LL, 128LL * CC, 3,
        x, (long long)CC * NN,
        (float*)p_qkv, (long long)C3 * NN);

    dwconv_k<<<dim3(48, C3, BB), dim3(48, 2)>>>(
        (const float*)p_qkv, dw_w, (float*)p_dw);

    gram_k<<<GR_BLOCKS, 256, GRAM_SMEM>>>((const float*)p_dw);

    fold_k<<<BB, 256>>>(proj_w, temp);

    // out = W_b @ v  (v = dw channels 256..383)
    gemm_k<<<dim3(NN / 128, BB), 256, GEMM_SMEM>>>(
        (const float*)p_W, (long long)CC * CC, 0LL, 1,
        (const float*)p_dw + 256LL * NN, (long long)C3 * NN,
        out, (long long)CC * NN);
}

// round 3
// speedup vs baseline: 1.5355x; 1.5355x over previous
#include <cuda_runtime.h>
#include <cstdint>

#define NN 110592
#define CC 128
#define C3 384
#define BB 2
#define GRB 296
#define GEMM_SMEM ((128 * 136 + 2 * 128 * 36) * 4)

__device__ float g_qkv[(size_t)BB * C3 * NN];
__device__ float g_dw [(size_t)BB * C3 * NN];
__device__ float g_gram[BB * 8 * 16 * 16];
__device__ float g_ssq [BB * 2 * CC];
__device__ float g_W   [BB * CC * CC];

__device__ __forceinline__ unsigned f2tf(float f) {
    unsigned u; asm("cvt.rna.tf32.f32 %0, %1;" : "=r"(u) : "f"(f)); return u;
}
__device__ __forceinline__ float f2tff(float f) { return __uint_as_float(f2tf(f)); }
__device__ __forceinline__ void mma8(float* d, const unsigned* a, const unsigned* b) {
    asm volatile("mma.sync.aligned.m16n8k8.row.col.f32.tf32.tf32.f32 "
                 "{%0,%1,%2,%3}, {%4,%5,%6,%7}, {%8,%9}, {%0,%1,%2,%3};"
                 : "+f"(d[0]), "+f"(d[1]), "+f"(d[2]), "+f"(d[3])
                 : "r"(a[0]), "r"(a[1]), "r"(a[2]), "r"(a[3]), "r"(b[0]), "r"(b[1]));
}

__global__ void zero_k() {
    int t = blockIdx.x * 256 + threadIdx.x;
    if (t < BB * 8 * 16 * 16) g_gram[t] = 0.f;
    if (t < BB * 2 * CC)      g_ssq[t]  = 0.f;
}

// ---------------- TF32 GEMM: C[mt] = A[mt](128x128) @ B(128 x 128-tile) ----------
__global__ __launch_bounds__(256, 2) void gemm_k(
    const float* __restrict__ A, long long aBatch, long long aTile, int MT,
    const float* __restrict__ B, long long bBatch,
    float* __restrict__ C, long long cBatch)
{
    extern __shared__ float sm[];
    float* sB = sm;               // [128][136] tf32-converted
    float* sA = sm + 128 * 136;   // [2][128][36] tf32-converted
    const int tid = threadIdx.x;
    const int bn = blockIdx.x, bb = blockIdx.y;
    const float* Ab = A + (long long)bb * aBatch;
    const float* Bb = B + (long long)bb * bBatch + (long long)bn * 128;
    float* Cb = C + (long long)bb * cBatch + (long long)bn * 128;

    // stage B once (cvt at store)
    {
        const int r0 = tid >> 5, c4 = tid & 31;
        #pragma unroll
        for (int i = 0; i < 16; i++) {
            int r = i * 8 + r0;
            float4 v = *(const float4*)(Bb + (long long)r * NN + c4 * 4);
            *(float4*)(&sB[r * 136 + c4 * 4]) =
                make_float4(f2tff(v.x), f2tff(v.y), f2tff(v.z), f2tff(v.w));
        }
    }

    const int ar = tid >> 3, ac = tid & 7;
    float4 rg[4];
    auto ldA = [&](int mt, int kt) {
        const float* At = Ab + (long long)mt * aTile + kt * 32;
        #pragma unroll
        for (int j = 0; j < 4; j++)
            rg[j] = *(const float4*)(At + (j * 32 + ar) * 128 + ac * 4);
    };
    auto stA = [&](int bufsel) {
        float* base = sA + bufsel * 128 * 36;
        #pragma unroll
        for (int j = 0; j < 4; j++)
            *(float4*)(base + (j * 32 + ar) * 36 + ac * 4) =
                make_float4(f2tff(rg[j].x), f2tff(rg[j].y), f2tff(rg[j].z), f2tff(rg[j].w));
    };

    ldA(0, 0);
    stA(0);
    __syncthreads();

    const int warp = tid >> 5, lane = tid & 31;
    const int wm = warp >> 2, wn = warp & 3;
    const int lr = lane >> 2, lc = lane & 3;

    int buf = 0;
    float acc[4][4][4];
    const int steps = MT * 4;
    for (int step = 0; step < steps; step++) {
        const int mt = step >> 2, kt = step & 3;
        if (kt == 0) {
            #pragma unroll
            for (int a = 0; a < 4; a++)
                #pragma unroll
                for (int b2 = 0; b2 < 4; b2++)
                    #pragma unroll
                    for (int r = 0; r < 4; r++) acc[a][b2][r] = 0.f;
        }
        const bool hasNext = (step + 1 < steps);
        if (hasNext) ldA((step + 1) >> 2, (step + 1) & 3);

        const float* sAb = sA + buf * 128 * 36;
        #pragma unroll
        for (int ks = 0; ks < 4; ks++) {
            const int k = ks * 8;
            const int kk = kt * 32 + k;
            unsigned af[4][4], bfr[4][2];
            #pragma unroll
            for (int mi = 0; mi < 4; mi++) {
                int m0 = wm * 64 + mi * 16;
                af[mi][0] = __float_as_uint(sAb[(m0 + lr) * 36 + k + lc]);
                af[mi][1] = __float_as_uint(sAb[(m0 + 8 + lr) * 36 + k + lc]);
                af[mi][2] = __float_as_uint(sAb[(m0 + lr) * 36 + k + 4 + lc]);
                af[mi][3] = __float_as_uint(sAb[(m0 + 8 + lr) * 36 + k + 4 + lc]);
            }
            #pragma unroll
            for (int ni = 0; ni < 4; ni++) {
                int n0 = wn * 32 + ni * 8;
                bfr[ni][0] = __float_as_uint(sB[(kk + lc) * 136 + n0 + lr]);
                bfr[ni][1] = __float_as_uint(sB[(kk + 4 + lc) * 136 + n0 + lr]);
            }
            #pragma unroll
            for (int mi = 0; mi < 4; mi++)
                #pragma unroll
                for (int ni = 0; ni < 4; ni++)
                    mma8(acc[mi][ni], af[mi], bfr[ni]);
        }
        if (hasNext) stA(buf ^ 1);
        __syncthreads();
        buf ^= 1;

        if (kt == 3) {
            #pragma unroll
            for (int mi = 0; mi < 4; mi++) {
                int m0 = mt * 128 + wm * 64 + mi * 16;
                #pragma unroll
                for (int ni = 0; ni < 4; ni++) {
                    int n0 = wn * 32 + ni * 8;
                    *(float2*)(Cb + (long long)(m0 + lr) * NN + n0 + lc * 2) =
                        make_float2(acc[mi][ni][0], acc[mi][ni][1]);
                    *(float2*)(Cb + (long long)(m0 + 8 + lr) * NN + n0 + lc * 2) =
                        make_float2(acc[mi][ni][2], acc[mi][ni][3]);
                }
            }
        }
    }
}

// ---------------- depthwise 3x3x3, sliding-plane over h -------------------------
// block = (hhalf, ch, b), threads (48 d, 4 w-groups). 4-plane smem ring, stride 60.
__global__ __launch_bounds__(192) void dwconv_k(
    const float* __restrict__ in, const float* __restrict__ wg,
    float* __restrict__ out)
{
    __shared__ float sP[4][50 * 60];
    __shared__ float sred[192];
    const int hhalf = blockIdx.x, ch = blockIdx.y, b = blockIdx.z;
    const int tx = threadIdx.x, ty = threadIdx.y;
    const int tid = ty * 48 + tx;
    const int h0 = hhalf * 24;

    for (int i = tid; i < 4 * 3000; i += 192) ((float*)sP)[i] = 0.f;

    float wv[27];
    const float* wp = wg + ch * 27;
    #pragma unroll
    for (int i = 0; i < 27; i++) wv[i] = wp[i];
    __syncthreads();

    const float* base = in + (long long)(b * C3 + ch) * 48 * 2304;
    auto loadPlane = [&](int slot, int hh) {
        const float* pl = base + (long long)hh * 2304;
        float* sp = sP[slot];
        #pragma unroll
        for (int j = 0; j < 3; j++) {
            int l = j * 192 + tid;
            int wr = l / 12, q = l % 12;
            float4 v = *(const float4*)(pl + wr * 48 + q * 4);
            *(float4*)(&sp[(wr + 1) * 60 + 4 + q * 4]) = v;
        }
    };
    auto zeroPlane = [&](int slot) {
        float* sp = sP[slot];
        for (int i = tid; i < 3000; i += 192) sp[i] = 0.f;
    };

    if (h0 - 1 >= 0) loadPlane(h0 & 3, h0 - 1);
    loadPlane((h0 + 1) & 3, h0);

    const int d = tx, w0 = ty * 12;
    float lssq = 0.f;
    float* ob0 = out + (long long)(b * C3 + ch) * 48 * 2304;

    for (int h = h0; h < h0 + 24; h++) {
        if (h + 1 < 48) loadPlane((h + 2) & 3, h + 1);
        else            zeroPlane((h + 2) & 3);
        __syncthreads();
        const float* P0 = sP[h & 3];
        const float* P1 = sP[(h + 1) & 3];
        const float* P2 = sP[(h + 2) & 3];

        float r[3][3][3];  // [w-slot][hp][dp]
        #pragma unroll
        for (int dp = 0; dp < 3; dp++) {
            r[0][0][dp] = P0[w0 * 60 + d + 3 + dp];
            r[0][1][dp] = P1[w0 * 60 + d + 3 + dp];
            r[0][2][dp] = P2[w0 * 60 + d + 3 + dp];
            r[1][0][dp] = P0[(w0 + 1) * 60 + d + 3 + dp];
            r[1][1][dp] = P1[(w0 + 1) * 60 + d + 3 + dp];
            r[1][2][dp] = P2[(w0 + 1) * 60 + d + 3 + dp];
        }
        float* ob = ob0 + (long long)h * 2304;
        #pragma unroll
        for (int k = 0; k < 12; k++) {
            const int ns = (k + 2) % 3;
            #pragma unroll
            for (int dp = 0; dp < 3; dp++) {
                r[ns][0][dp] = P0[(w0 + k + 2) * 60 + d + 3 + dp];
                r[ns][1][dp] = P1[(w0 + k + 2) * 60 + d + 3 + dp];
                r[ns][2][dp] = P2[(w0 + k + 2) * 60 + d + 3 + dp];
            }
            float o = 0.f;
            #pragma unroll
            for (int hp = 0; hp < 3; hp++)
                #pragma unroll
                for (int q = 0; q < 3; q++) {
                    const int sl = (k + q) % 3;
                    #pragma unroll
                    for (int dp = 0; dp < 3; dp++)
                        o += wv[hp * 9 + q * 3 + dp] * r[sl][hp][dp];
                }
            ob[(w0 + k) * 48 + d] = o;
            lssq += o * o;
        }
    }

    if (ch < 256) {
        sred[tid] = lssq;
        __syncthreads();
        if (tid < 32) {
            float v = sred[tid] + sred[tid + 32] + sred[tid + 64]
                    + sred[tid + 96] + sred[tid + 128] + sred[tid + 160];
            #pragma unroll
            for (int off = 16; off > 0; off >>= 1)
                v += __shfl_down_sync(0xffffffffu, v, off);
            if (tid == 0) atomicAdd(&g_ssq[b * 256 + ch], v);
        }
    }
}

// ---------------- Gram: G[b,h,i,j] = sum_n q[i,n]*k[j,n] ------------------------
// column-major smem sq[n][ch], stride 257 (conflict-free stores + reads).
__global__ __launch_bounds__(256) void gram_k(const float* __restrict__ dw) {
    __shared__ float sq[32 * 257];
    const int tid = threadIdx.x;
    const int b = blockIdx.y;
    const int warp = tid >> 5, lane = tid & 31;
    const int lr4 = lane >> 3, lq = lane & 7;
    const float* dwb = dw + (long long)b * C3 * NN;

    float4 rg[8];
    auto ldC = [&](int c) {
        long long n0 = (long long)c * 32;
        #pragma unroll
        for (int j = 0; j < 8; j++) {
            int row = warp * 32 + j * 4 + lr4;
            rg[j] = *(const float4*)(dwb + (long long)row * NN + n0 + lq * 4);
        }
    };
    auto stC = [&]() {
        #pragma unroll
        for (int j = 0; j < 8; j++) {
            int row = warp * 32 + j * 4 + lr4;
            sq[(lq * 4 + 0) * 257 + row] = rg[j].x;
            sq[(lq * 4 + 1) * 257 + row] = rg[j].y;
            sq[(lq * 4 + 2) * 257 + row] = rg[j].z;
            sq[(lq * 4 + 3) * 257 + row] = rg[j].w;
        }
    };

    const int h = warp;
    const int it = lane >> 3, jt = (lane >> 1) & 3, nh = lane & 1;
    const int qb = h * 16 + it * 4, kb = 128 + h * 16 + jt * 4;
    float acc[4][4];
    #pragma unroll
    for (int a = 0; a < 4; a++)
        #pragma unroll
        for (int c = 0; c < 4; c++) acc[a][c] = 0.f;

    int c = blockIdx.x;
    ldC(c);
    while (1) {
        stC();
        __syncthreads();
        int cn = c + GRB;
        bool more = cn < NN / 32;
        if (more) ldC(cn);
        #pragma unroll 4
        for (int s = 0; s < 16; s++) {
            const float* rowp = sq + (2 * s + nh) * 257;
            float qv[4], kv[4];
            #pragma unroll
            for (int ii = 0; ii < 4; ii++) qv[ii] = rowp[qb + ii];
            #pragma unroll
            for (int jj = 0; jj < 4; jj++) kv[jj] = rowp[kb + jj];
            #pragma unroll
            for (int ii = 0; ii < 4; ii++)
                #pragma unroll
                for (int jj = 0; jj < 4; jj++)
                    acc[ii][jj] += qv[ii] * kv[jj];
        }
        __syncthreads();
        if (!more) break;
        c = cn;
    }
    #pragma unroll
    for (int ii = 0; ii < 4; ii++)
        #pragma unroll
        for (int jj = 0; jj < 4; jj++)
            acc[ii][jj] += __shfl_xor_sync(0xffffffffu, acc[ii][jj], 1);
    if (nh == 0) {
        #pragma unroll
        for (int ii = 0; ii < 4; ii++)
            #pragma unroll
            for (int jj = 0; jj < 4; jj++)
                atomicAdd(&g_gram[((b * 8 + h) * 16 + it * 4 + ii) * 16 + jt * 4 + jj],
                          acc[ii][jj]);
    }
}

// ---------------- softmax + W_b = proj_w @ blockdiag(attn_b) --------------------
__global__ __launch_bounds__(256) void fold_k(
    const float* __restrict__ proj_w, const float* __restrict__ temp)
{
    __shared__ float sat[8][16][17];
    const int b = blockIdx.x, tid = threadIdx.x;
    if (tid < 128) {
        const int h = tid >> 4, i = tid & 15;
        float nq = fmaxf(sqrtf(g_ssq[b * 256 + h * 16 + i]), 1e-12f);
        float tv = temp[h];
        float row[16];
        float mx = -1e30f;
        #pragma unroll
        for (int j = 0; j < 16; j++) {
            float nk = fmaxf(sqrtf(g_ssq[b * 256 + 128 + h * 16 + j]), 1e-12f);
            float v = g_gram[((b * 8 + h) * 16 + i) * 16 + j] / (nq * nk) * tv;
            row[j] = v;
            mx = fmaxf(mx, v);
        }
        float s = 0.f;
        #pragma unroll
        for (int j = 0; j < 16; j++) { row[j] = expf(row[j] - mx); s += row[j]; }
        const float inv = 1.f / s;
        #pragma unroll
        for (int j = 0; j < 16; j++) sat[h][i][j] = row[j] * inv;
    }
    __syncthreads();
    for (int idx = tid; idx < 16384; idx += 256) {
        const int o = idx >> 7, col = idx & 127;
        const int h = col >> 4, j = col & 15;
        float s = 0.f;
        #pragma unroll
        for (int i = 0; i < 16; i++)
            s += proj_w[o * 128 + h * 16 + i] * sat[h][i][j];
        g_W[b * 16384 + idx] = s;
    }
}

extern "C" void kernel_launch(void* const* d_in, const int* in_sizes, int n_in,
                              void* d_out, int out_size) {
    const float* x      = (const float*)d_in[0];
    const float* qkv_w  = (const float*)d_in[1];
    const float* dw_w   = (const float*)d_in[2];
    const float* proj_w = (const float*)d_in[3];
    const float* temp   = (const float*)d_in[4];
    float* out = (float*)d_out;

    void *p_qkv = nullptr, *p_dw = nullptr, *p_W = nullptr;
    cudaGetSymbolAddress(&p_qkv, g_qkv);
    cudaGetSymbolAddress(&p_dw,  g_dw);
    cudaGetSymbolAddress(&p_W,   g_W);

    cudaFuncSetAttribute(gemm_k, cudaFuncAttributeMaxDynamicSharedMemorySize, GEMM_SMEM);

    zero_k<<<16, 256>>>();

    gemm_k<<<dim3(NN / 128, BB), 256, GEMM_SMEM>>>(
        qkv_w, 0LL, 128LL * CC, 3,
        x, (long long)CC * NN,
        (float*)p_qkv, (long long)C3 * NN);

    dwconv_k<<<dim3(2, C3, BB), dim3(48, 4)>>>(
        (const float*)p_qkv, dw_w, (float*)p_dw);

    gram_k<<<dim3(GRB, BB), 256>>>((const float*)p_dw);

    fold_k<<<BB, 256>>>(proj_w, temp);

    gemm_k<<<dim3(NN / 128, BB), 256, GEMM_SMEM>>>(
        (const float*)p_W, (long long)CC * CC, 0LL, 1,
        (const float*)p_dw + 256LL * NN, (long long)C3 * NN,
        out, (long long)CC * NN);
}